// round 6
// baseline (speedup 1.0000x reference)
#include <cuda_runtime.h>
#include <cstdint>

#define NN     10000
#define NE     320000
#define H      128
#define HID    256
#define KM     336   // 2*H + 64 + 16  (F row width)
#define KX     384   // H + HID
#define KA     464   // H + KM         (fused GEMM K)
#define NSTEP  64
#define NLAYER 4

// ---------------- static device scratch ----------------
__device__ float g_F[(size_t)NN * KM];             // [cnt*x | Σx_j | Σsoh | Σea]
__device__ float g_xbuf[2][(size_t)NN * H];
__device__ float g_posbuf[2][(size_t)NN * 3];
__device__ int   g_cnt[NN];
__device__ int   g_rowbeg[NN];
__device__ int   g_cursor[NN];
__device__ int   g_colj[NE];
__device__ float g_cntf[NN];
__device__ int   g_total[1];
__device__ float g_Wallh[(size_t)NLAYER * KA * H]; // tf32-hi of [Wx1 ; Wm@Wx2]
__device__ float g_Wallo[(size_t)NLAYER * KA * H]; // tf32-lo remainder
__device__ float g_bmx[NLAYER * H];                // bm @ Wx2

__device__ __forceinline__ float leaky(float v) { return v > 0.f ? v : 0.01f * v; }
__device__ __forceinline__ float tf32_rna(float x) {
    float r; asm("cvt.rna.tf32.f32 %0, %1;" : "=f"(r) : "f"(x)); return r;
}
__device__ __forceinline__ void mma8(float* d, const uint32_t* a, const uint32_t* b) {
    asm volatile(
        "mma.sync.aligned.m16n8k8.row.col.f32.tf32.tf32.f32 "
        "{%0,%1,%2,%3}, {%4,%5,%6,%7}, {%8,%9}, {%0,%1,%2,%3};"
        : "+f"(d[0]), "+f"(d[1]), "+f"(d[2]), "+f"(d[3])
        : "r"(a[0]), "r"(a[1]), "r"(a[2]), "r"(a[3]), "r"(b[0]), "r"(b[1]));
}

// ---------------- preamble kernels ----------------
__global__ void zero_init(float* __restrict__ F, int* __restrict__ cnt, int* __restrict__ total) {
    int idx = blockIdx.x * blockDim.x + threadIdx.x;
    if (idx < NN * 16) F[(size_t)(idx >> 4) * KM + 320 + (idx & 15)] = 0.f;
    if (idx < NN) cnt[idx] = 0;
    if (idx == 0) total[0] = 0;
}

__global__ void edge_pre(const int* __restrict__ ei, const float* __restrict__ ea,
                         int* __restrict__ cnt, float* __restrict__ F) {
    int idx = blockIdx.x * blockDim.x + threadIdx.x;
    if (idx < NE * 16) {
        int e = idx >> 4, k = idx & 15;
        int dst = ei[e];
        atomicAdd(&F[(size_t)dst * KM + 320 + k], ea[idx]);
        if (k == 0) atomicAdd(&cnt[dst], 1);
    }
}

// parallel segment allocation: warp scan + one atomic per warp (order-free CSR)
__global__ void alloc_rows(const int* __restrict__ cnt, int* __restrict__ rowbeg,
                           int* __restrict__ cursor, float* __restrict__ cntf,
                           int* __restrict__ total) {
    int n = blockIdx.x * blockDim.x + threadIdx.x;
    int lane = threadIdx.x & 31;
    int v = (n < NN) ? cnt[n] : 0;
    int sc = v;
#pragma unroll
    for (int o = 1; o < 32; o <<= 1) {
        int u = __shfl_up_sync(0xffffffffu, sc, o);
        if (lane >= o) sc += u;
    }
    int wsum = __shfl_sync(0xffffffffu, sc, 31);
    int base = 0;
    if (lane == 0) base = atomicAdd(total, wsum);
    base = __shfl_sync(0xffffffffu, base, 0);
    int beg = base + sc - v;
    if (n < NN) { rowbeg[n] = beg; cursor[n] = beg; cntf[n] = (float)v; }
}

__global__ void build_csr(const int* __restrict__ ei, int* __restrict__ cursor,
                          int* __restrict__ colj) {
    int e = blockIdx.x * blockDim.x + threadIdx.x;
    if (e < NE) {
        int p = atomicAdd(&cursor[ei[e]], 1);
        colj[p] = ei[NE + e];
    }
}

// fold Wm through Wx2 AND pre-split into tf32 hi/lo:
// Wall[l] = [ Wx1 ; Wm@Wx2 ]  ->  Wallh (rna) + Wallo (rna of remainder); bmx[l] = bm@Wx2
__global__ void prep_weights(const float* __restrict__ Wm, const float* __restrict__ bm,
                             const float* __restrict__ Wx,
                             float* __restrict__ Wallh, float* __restrict__ Wallo,
                             float* __restrict__ bmx) {
    int l = blockIdx.x, y = blockIdx.y, n = threadIdx.x;
    const float* WxL = Wx + (size_t)l * KX * H;
    if (y < KA) {
        float w;
        if (y < H) {
            w = WxL[(size_t)y * H + n];
        } else {
            int r = y - H;
            const float* wm = Wm + (size_t)l * KM * HID + (size_t)r * HID;
            float s = 0.f;
#pragma unroll 8
            for (int h = 0; h < HID; h++) s += wm[h] * WxL[(size_t)(H + h) * H + n];
            w = s;
        }
        float hi = tf32_rna(w);
        size_t o = (size_t)l * KA * H + (size_t)y * H + n;
        Wallh[o] = hi;
        Wallo[o] = tf32_rna(w - hi);
    } else {
        const float* bmL = bm + (size_t)l * HID;
        float s = 0.f;
#pragma unroll 8
        for (int h = 0; h < HID; h++) s += bmL[h] * WxL[(size_t)(H + h) * H + n];
        bmx[l * H + n] = s;
    }
}

// ---------------- per-layer CSR kernel: one warp per node ----------------
__global__ __launch_bounds__(256) void csr_layer(
    const float* __restrict__ x, const float* __restrict__ pos,
    const int* __restrict__ rowbeg, const int* __restrict__ colj,
    const float* __restrict__ cntf, float* __restrict__ F, float* __restrict__ npos)
{
    int w = (blockIdx.x * blockDim.x + threadIdx.x) >> 5;
    int lane = threadIdx.x & 31;
    if (w >= NN) return;
    int beg = rowbeg[w];
    float cf = cntf[w];
    int end = beg + (int)cf;
    float4 xi = ((const float4*)(x + (size_t)w * H))[lane];
    float4 xs = make_float4(0.f, 0.f, 0.f, 0.f);
    float s0 = 0.f, s1 = 0.f, ps = 0.f;
    const float step = 10.f / 63.f;
    float c0 = (2 * lane) * step, c1 = (2 * lane + 1) * step;

    int jn = 0, jn2 = 0;
    float4 xjn = make_float4(0.f, 0.f, 0.f, 0.f);
    float pjn = 0.f;
    if (beg < end) {
        jn = colj[beg];
        xjn = ((const float4*)(x + (size_t)jn * H))[lane];
        if (lane < 3) pjn = pos[jn * 3 + lane];
    }
    if (beg + 1 < end) jn2 = colj[beg + 1];

    for (int k = beg; k < end; k++) {
        float4 xj = xjn;
        float pj = pjn;
        int jcur = jn2;
        jn = jn2;
        if (k + 2 < end) jn2 = colj[k + 2];
        if (k + 1 < end) {
            xjn = ((const float4*)(x + (size_t)jcur * H))[lane];
            if (lane < 3) pjn = pos[jcur * 3 + lane];
        }
        float dx = xi.x - xj.x, dy = xi.y - xj.y, dz = xi.z - xj.z, dw = xi.w - xj.w;
        float ss = dx * dx + dy * dy + dz * dz + dw * dw;
#pragma unroll
        for (int o = 16; o; o >>= 1) ss += __shfl_xor_sync(0xffffffffu, ss, o);
        float r = sqrtf(ss);
        float d0 = r - c0, d1 = r - c1;
        s0 += __expf(-10.f * d0 * d0);
        s1 += __expf(-10.f * d1 * d1);
        xs.x += xj.x; xs.y += xj.y; xs.z += xj.z; xs.w += xj.w;
        ps += pj;
    }

    float* Fr = F + (size_t)w * KM;
    ((float4*)Fr)[lane]           = make_float4(cf * xi.x, cf * xi.y, cf * xi.z, cf * xi.w);
    ((float4*)(Fr + H))[lane]     = xs;
    ((float2*)(Fr + 2 * H))[lane] = make_float2(s0, s1);
    if (lane < 3) {
        float p = pos[w * 3 + lane];
        npos[w * 3 + lane] = p + (cf * p - ps) / fmaxf(cf, 1.f);
    }
}

// ---------------- fused layer GEMM (3xTF32 tensor cores, pre-split B) ----------------
// x' = leaky([x|F] @ Wall + bx + cnt*bmx)   [NN,464]@[464,128]
// BM=64 BN=128 BK=16, 256 thr, 8 warps (2x4), warp tile 32x32
#define NKT 29   // KA/16
__global__ __launch_bounds__(256) void fused_layer_gemm(
    const float* __restrict__ x, const float* __restrict__ F,
    const float* __restrict__ Wallh, const float* __restrict__ Wallo,
    const float* __restrict__ bx, const float* __restrict__ bmx,
    const float* __restrict__ cntf,
    const float* __restrict__ resid, float* __restrict__ xout)
{
    __shared__ float Ah[64][20], Al[64][20];
    __shared__ float Bh[16][136], Bl[16][136];

    int t = threadIdx.x;
    int m0 = blockIdx.x * 64;
    int wid = t >> 5, lane = t & 31;
    int g = lane >> 2, c = lane & 3;
    int mb = (wid >> 2) * 32, nb = (wid & 3) * 32;

    // loader coords
    int am = t & 63, akq = (t >> 6) << 2;           // A: row am, 4 k
    int bk = t >> 4, bn = (t & 15) << 3;            // B: row bk, 8 n
    int mm = m0 + am; if (mm >= NN) mm = NN - 1;
    const float* rowx = x + (size_t)mm * H;
    const float* rowF = F + (size_t)mm * KM - H;    // rowF[k] = F[m][k-128]

    float acc[2][4][4];
#pragma unroll
    for (int i = 0; i < 2; i++)
#pragma unroll
        for (int j = 0; j < 4; j++)
#pragma unroll
            for (int q = 0; q < 4; q++) acc[i][j][q] = 0.f;

    // preload tile 0
    float4 aR, bh0, bh1, bl0, bl1;
    {
        int k = akq;
        aR = *(const float4*)((k < H ? rowx : rowF) + k);
        size_t bo = (size_t)bk * H + bn;
        bh0 = *(const float4*)(Wallh + bo);
        bh1 = *(const float4*)(Wallh + bo + 4);
        bl0 = *(const float4*)(Wallo + bo);
        bl1 = *(const float4*)(Wallo + bo + 4);
    }

    for (int it = 0; it < NKT; it++) {
        // split A + store; B copied directly (pre-split offline)
        {
            float h0 = tf32_rna(aR.x), h1 = tf32_rna(aR.y),
                  h2 = tf32_rna(aR.z), h3 = tf32_rna(aR.w);
            Ah[am][akq+0] = h0; Ah[am][akq+1] = h1; Ah[am][akq+2] = h2; Ah[am][akq+3] = h3;
            Al[am][akq+0] = tf32_rna(aR.x - h0); Al[am][akq+1] = tf32_rna(aR.y - h1);
            Al[am][akq+2] = tf32_rna(aR.z - h2); Al[am][akq+3] = tf32_rna(aR.w - h3);

            *(float4*)&Bh[bk][bn]     = bh0;
            *(float4*)&Bh[bk][bn + 4] = bh1;
            *(float4*)&Bl[bk][bn]     = bl0;
            *(float4*)&Bl[bk][bn + 4] = bl1;
        }
        __syncthreads();

        // prefetch next tile
        if (it + 1 < NKT) {
            int k0n = (it + 1) * 16;
            int k = k0n + akq;
            aR = *(const float4*)((k < H ? rowx : rowF) + k);
            size_t bo = (size_t)(k0n + bk) * H + bn;
            bh0 = *(const float4*)(Wallh + bo);
            bh1 = *(const float4*)(Wallh + bo + 4);
            bl0 = *(const float4*)(Wallo + bo);
            bl1 = *(const float4*)(Wallo + bo + 4);
        }

        // compute: 2 k8 sub-steps
#pragma unroll
        for (int ks = 0; ks < 16; ks += 8) {
            uint32_t ah[2][4], al[2][4], bhf[4][2], blf[4][2];
#pragma unroll
            for (int mt = 0; mt < 2; mt++) {
                int r0 = mb + mt * 16 + g, r1 = r0 + 8;
                ah[mt][0] = __float_as_uint(Ah[r0][ks + c]);
                ah[mt][1] = __float_as_uint(Ah[r1][ks + c]);
                ah[mt][2] = __float_as_uint(Ah[r0][ks + c + 4]);
                ah[mt][3] = __float_as_uint(Ah[r1][ks + c + 4]);
                al[mt][0] = __float_as_uint(Al[r0][ks + c]);
                al[mt][1] = __float_as_uint(Al[r1][ks + c]);
                al[mt][2] = __float_as_uint(Al[r0][ks + c + 4]);
                al[mt][3] = __float_as_uint(Al[r1][ks + c + 4]);
            }
#pragma unroll
            for (int nt = 0; nt < 4; nt++) {
                int nc = nb + nt * 8 + g;
                bhf[nt][0] = __float_as_uint(Bh[ks + c][nc]);
                bhf[nt][1] = __float_as_uint(Bh[ks + c + 4][nc]);
                blf[nt][0] = __float_as_uint(Bl[ks + c][nc]);
                blf[nt][1] = __float_as_uint(Bl[ks + c + 4][nc]);
            }
#pragma unroll
            for (int mt = 0; mt < 2; mt++)
#pragma unroll
                for (int nt = 0; nt < 4; nt++) {
                    mma8(acc[mt][nt], al[mt], bhf[nt]);   // lo*hi
                    mma8(acc[mt][nt], ah[mt], blf[nt]);   // hi*lo
                    mma8(acc[mt][nt], ah[mt], bhf[nt]);   // hi*hi
                }
        }
        __syncthreads();
    }

    // epilogue
#pragma unroll
    for (int mt = 0; mt < 2; mt++) {
        int r0 = m0 + mb + mt * 16 + g;
        int r1 = r0 + 8;
        float cf0 = (r0 < NN) ? cntf[r0] : 0.f;
        float cf1 = (r1 < NN) ? cntf[r1] : 0.f;
#pragma unroll
        for (int nt = 0; nt < 4; nt++) {
            int col = nb + nt * 8 + 2 * c;
            float bx0 = bx[col], bx1 = bx[col + 1];
            float bm0 = bmx[col], bm1 = bmx[col + 1];
            if (r0 < NN) {
                float v0 = leaky(acc[mt][nt][0] + bx0 + cf0 * bm0);
                float v1 = leaky(acc[mt][nt][1] + bx1 + cf0 * bm1);
                if (resid) {
                    v0 = leaky(resid[(size_t)r0 * H + col] + v0);
                    v1 = leaky(resid[(size_t)r0 * H + col + 1] + v1);
                }
                *(float2*)&xout[(size_t)r0 * H + col] = make_float2(v0, v1);
            }
            if (r1 < NN) {
                float v2 = leaky(acc[mt][nt][2] + bx0 + cf1 * bm0);
                float v3 = leaky(acc[mt][nt][3] + bx1 + cf1 * bm1);
                if (resid) {
                    v2 = leaky(resid[(size_t)r1 * H + col] + v2);
                    v3 = leaky(resid[(size_t)r1 * H + col + 1] + v3);
                }
                *(float2*)&xout[(size_t)r1 * H + col] = make_float2(v2, v3);
            }
        }
    }
}

// ---------------- launch ----------------
extern "C" void kernel_launch(void* const* d_in, const int* in_sizes, int n_in,
                              void* d_out, int out_size) {
    const float* x   = (const float*)d_in[0];
    const float* pos = (const float*)d_in[1];
    const int*   ei  = (const int*)d_in[2];
    const float* ea  = (const float*)d_in[3];
    const float* Wm  = (const float*)d_in[4];
    const float* bm  = (const float*)d_in[5];
    // d_in[6] = Wp, d_in[7] = bp : dead code (alpha unused)
    const float* Wx  = (const float*)d_in[8];
    const float* bx  = (const float*)d_in[9];
    float* out = (float*)d_out;

    float *F, *xb, *pb, *cntf, *Wallh, *Wallo, *bmx;
    int *cnt, *rowbeg, *cursor, *colj, *total;
    cudaGetSymbolAddress((void**)&F,      g_F);
    cudaGetSymbolAddress((void**)&xb,     g_xbuf);
    cudaGetSymbolAddress((void**)&pb,     g_posbuf);
    cudaGetSymbolAddress((void**)&cnt,    g_cnt);
    cudaGetSymbolAddress((void**)&rowbeg, g_rowbeg);
    cudaGetSymbolAddress((void**)&cursor, g_cursor);
    cudaGetSymbolAddress((void**)&colj,   g_colj);
    cudaGetSymbolAddress((void**)&cntf,   g_cntf);
    cudaGetSymbolAddress((void**)&total,  g_total);
    cudaGetSymbolAddress((void**)&Wallh,  g_Wallh);
    cudaGetSymbolAddress((void**)&Wallo,  g_Wallo);
    cudaGetSymbolAddress((void**)&bmx,    g_bmx);

    // preamble: CSR build (order-free segments) + weight folding/splitting
    zero_init<<<(NN * 16 + 255) / 256, 256>>>(F, cnt, total);
    edge_pre<<<(NE * 16 + 255) / 256, 256>>>(ei, ea, cnt, F);
    alloc_rows<<<(NN + 255) / 256, 256>>>(cnt, rowbeg, cursor, cntf, total);
    build_csr<<<(NE + 255) / 256, 256>>>(ei, cursor, colj);
    {
        dim3 gp(NLAYER, KA + 1);
        prep_weights<<<gp, 128>>>(Wm, bm, Wx, Wallh, Wallo, bmx);
    }

    const float* curx = x;
    const float* curp = pos;
    for (int l = 0; l < NLAYER; l++) {
        bool last = (l == NLAYER - 1);
        float* nx = last ? out : xb + (size_t)(l & 1) * NN * H;
        float* np = last ? out + (size_t)NN * H : pb + (size_t)(l & 1) * NN * 3;

        csr_layer<<<(NN * 32 + 255) / 256, 256>>>(curx, curp, rowbeg, colj, cntf, F, np);
        fused_layer_gemm<<<(NN + 63) / 64, 256>>>(curx, F,
                                                  Wallh + (size_t)l * KA * H,
                                                  Wallo + (size_t)l * KA * H,
                                                  bx + (size_t)l * H, bmx + l * H,
                                                  cntf, last ? x : nullptr, nx);
        curx = nx;
        curp = np;
    }
}

// round 7
// speedup vs baseline: 1.6356x; 1.6356x over previous
#include <cuda_runtime.h>
#include <cstdint>

#define NN     10000
#define NE     320000
#define H      128
#define HID    256
#define KM     336   // 2*H + 64 + 16  (F row width)
#define KX     384   // H + HID
#define KA     464   // H + KM         (fused GEMM K)
#define NSTEP  64
#define NLAYER 4

// ---------------- static device scratch ----------------
__device__ float g_F[(size_t)NN * KM];             // [cnt*x | Σx_j | Σsoh | Σea]
__device__ float g_xbuf[2][(size_t)NN * H];
__device__ float g_posbuf[2][(size_t)NN * 3];
__device__ int   g_cnt[NN];
__device__ int   g_rowbeg[NN];
__device__ int   g_cursor[NN];
__device__ int   g_colj[NE];
__device__ float g_cntf[NN];
__device__ int   g_total[1];
__device__ float g_Wall[(size_t)NLAYER * KA * H];  // [Wx1 ; Wm@Wx2]
__device__ float g_bmx[NLAYER * H];                // bm @ Wx2

__device__ __forceinline__ float leaky(float v) { return v > 0.f ? v : 0.01f * v; }
__device__ __forceinline__ float tf32_rna(float x) {
    float r; asm("cvt.rna.tf32.f32 %0, %1;" : "=f"(r) : "f"(x)); return r;
}
__device__ __forceinline__ void mma8(float* d, const uint32_t* a, const uint32_t* b) {
    asm volatile(
        "mma.sync.aligned.m16n8k8.row.col.f32.tf32.tf32.f32 "
        "{%0,%1,%2,%3}, {%4,%5,%6,%7}, {%8,%9}, {%0,%1,%2,%3};"
        : "+f"(d[0]), "+f"(d[1]), "+f"(d[2]), "+f"(d[3])
        : "r"(a[0]), "r"(a[1]), "r"(a[2]), "r"(a[3]), "r"(b[0]), "r"(b[1]));
}

// ---------------- preamble kernels ----------------
__global__ void zero_init(float* __restrict__ F, int* __restrict__ cnt, int* __restrict__ total) {
    int idx = blockIdx.x * blockDim.x + threadIdx.x;
    if (idx < NN * 16) F[(size_t)(idx >> 4) * KM + 320 + (idx & 15)] = 0.f;
    if (idx < NN) cnt[idx] = 0;
    if (idx == 0) total[0] = 0;
}

__global__ void edge_pre(const int* __restrict__ ei, const float* __restrict__ ea,
                         int* __restrict__ cnt, float* __restrict__ F) {
    int idx = blockIdx.x * blockDim.x + threadIdx.x;
    if (idx < NE * 16) {
        int e = idx >> 4, k = idx & 15;
        int dst = ei[e];
        atomicAdd(&F[(size_t)dst * KM + 320 + k], ea[idx]);
        if (k == 0) atomicAdd(&cnt[dst], 1);
    }
}

// parallel segment allocation: warp scan + one atomic per warp (order-free CSR)
__global__ void alloc_rows(const int* __restrict__ cnt, int* __restrict__ rowbeg,
                           int* __restrict__ cursor, float* __restrict__ cntf,
                           int* __restrict__ total) {
    int n = blockIdx.x * blockDim.x + threadIdx.x;
    int lane = threadIdx.x & 31;
    int v = (n < NN) ? cnt[n] : 0;
    int sc = v;
#pragma unroll
    for (int o = 1; o < 32; o <<= 1) {
        int u = __shfl_up_sync(0xffffffffu, sc, o);
        if (lane >= o) sc += u;
    }
    int wsum = __shfl_sync(0xffffffffu, sc, 31);
    int base = 0;
    if (lane == 0) base = atomicAdd(total, wsum);
    base = __shfl_sync(0xffffffffu, base, 0);
    int beg = base + sc - v;
    if (n < NN) { rowbeg[n] = beg; cursor[n] = beg; cntf[n] = (float)v; }
}

__global__ void build_csr(const int* __restrict__ ei, int* __restrict__ cursor,
                          int* __restrict__ colj) {
    int e = blockIdx.x * blockDim.x + threadIdx.x;
    if (e < NE) {
        int p = atomicAdd(&cursor[ei[e]], 1);
        colj[p] = ei[NE + e];
    }
}

// fold Wm through Wx2:  Wall[l] = [ Wx1 ; Wm@Wx2 ],  bmx[l] = bm@Wx2
__global__ void prep_weights(const float* __restrict__ Wm, const float* __restrict__ bm,
                             const float* __restrict__ Wx,
                             float* __restrict__ Wall, float* __restrict__ bmx) {
    int l = blockIdx.x, y = blockIdx.y, n = threadIdx.x;
    const float* WxL = Wx + (size_t)l * KX * H;
    float* WallL = Wall + (size_t)l * KA * H;
    if (y < H) {
        WallL[(size_t)y * H + n] = WxL[(size_t)y * H + n];
    } else if (y < KA) {
        int r = y - H;
        const float* wm = Wm + (size_t)l * KM * HID + (size_t)r * HID;
        float s = 0.f;
#pragma unroll 8
        for (int h = 0; h < HID; h++) s += wm[h] * WxL[(size_t)(H + h) * H + n];
        WallL[(size_t)y * H + n] = s;
    } else {
        const float* bmL = bm + (size_t)l * HID;
        float s = 0.f;
#pragma unroll 8
        for (int h = 0; h < HID; h++) s += bmL[h] * WxL[(size_t)(H + h) * H + n];
        bmx[l * H + n] = s;
    }
}

// ---------------- per-layer CSR kernel: one warp per node ----------------
__global__ __launch_bounds__(256) void csr_layer(
    const float* __restrict__ x, const float* __restrict__ pos,
    const int* __restrict__ rowbeg, const int* __restrict__ colj,
    const float* __restrict__ cntf, float* __restrict__ F, float* __restrict__ npos)
{
    int w = (blockIdx.x * blockDim.x + threadIdx.x) >> 5;
    int lane = threadIdx.x & 31;
    if (w >= NN) return;
    int beg = rowbeg[w];
    float cf = cntf[w];
    int end = beg + (int)cf;
    float4 xi = ((const float4*)(x + (size_t)w * H))[lane];
    float4 xs = make_float4(0.f, 0.f, 0.f, 0.f);
    float s0 = 0.f, s1 = 0.f, ps = 0.f;
    const float step = 10.f / 63.f;
    float c0 = (2 * lane) * step, c1 = (2 * lane + 1) * step;

    int jn = 0, jn2 = 0;
    float4 xjn = make_float4(0.f, 0.f, 0.f, 0.f);
    float pjn = 0.f;
    if (beg < end) {
        jn = colj[beg];
        xjn = ((const float4*)(x + (size_t)jn * H))[lane];
        if (lane < 3) pjn = pos[jn * 3 + lane];
    }
    if (beg + 1 < end) jn2 = colj[beg + 1];

    for (int k = beg; k < end; k++) {
        float4 xj = xjn;
        float pj = pjn;
        int jcur = jn2;
        jn = jn2;
        if (k + 2 < end) jn2 = colj[k + 2];
        if (k + 1 < end) {
            xjn = ((const float4*)(x + (size_t)jcur * H))[lane];
            if (lane < 3) pjn = pos[jcur * 3 + lane];
        }
        float dx = xi.x - xj.x, dy = xi.y - xj.y, dz = xi.z - xj.z, dw = xi.w - xj.w;
        float ss = dx * dx + dy * dy + dz * dz + dw * dw;
#pragma unroll
        for (int o = 16; o; o >>= 1) ss += __shfl_xor_sync(0xffffffffu, ss, o);
        float r = sqrtf(ss);
        float d0 = r - c0, d1 = r - c1;
        s0 += __expf(-10.f * d0 * d0);
        s1 += __expf(-10.f * d1 * d1);
        xs.x += xj.x; xs.y += xj.y; xs.z += xj.z; xs.w += xj.w;
        ps += pj;
    }

    float* Fr = F + (size_t)w * KM;
    ((float4*)Fr)[lane]           = make_float4(cf * xi.x, cf * xi.y, cf * xi.z, cf * xi.w);
    ((float4*)(Fr + H))[lane]     = xs;
    ((float2*)(Fr + 2 * H))[lane] = make_float2(s0, s1);
    if (lane < 3) {
        float p = pos[w * 3 + lane];
        npos[w * 3 + lane] = p + (cf * p - ps) / fmaxf(cf, 1.f);
    }
}

// ---------------- fused layer GEMM (3xTF32 tensor cores) — R5 loader form ----------------
// x' = leaky([x|F] @ Wall + bx + cnt*bmx)   [NN,464]@[464,128]
// BM=64 BN=128 BK=16, 256 thr, 8 warps (2x4), warp tile 32x32
#define NKT 29   // KA/16
__global__ __launch_bounds__(256) void fused_layer_gemm(
    const float* __restrict__ x, const float* __restrict__ F,
    const float* __restrict__ Wall, const float* __restrict__ bx,
    const float* __restrict__ bmx, const float* __restrict__ cntf,
    const float* __restrict__ resid, float* __restrict__ xout)
{
    __shared__ float Ah[64][20], Al[64][20];
    __shared__ float Bh[16][136], Bl[16][136];

    int t = threadIdx.x;
    int m0 = blockIdx.x * 64;
    int wid = t >> 5, lane = t & 31;
    int g = lane >> 2, c = lane & 3;
    int mb = (wid >> 2) * 32, nb = (wid & 3) * 32;

    // loader coords
    int am = t & 63, akq = (t >> 6) << 2;           // A: row am, 4 k
    int bk = t >> 4, bn = (t & 15) << 3;            // B: row bk, 8 n
    int mm = m0 + am; if (mm >= NN) mm = NN - 1;
    const float* rowx = x + (size_t)mm * H;
    const float* rowF = F + (size_t)mm * KM - H;    // rowF[k] = F[m][k-128]

    float acc[2][4][4];
#pragma unroll
    for (int i = 0; i < 2; i++)
#pragma unroll
        for (int j = 0; j < 4; j++)
#pragma unroll
            for (int q = 0; q < 4; q++) acc[i][j][q] = 0.f;

    // preload tile 0
    float4 aR, bR0, bR1;
    {
        int k = akq;
        aR = *(const float4*)((k < H ? rowx : rowF) + k);
        const float* wsrc = Wall + (size_t)bk * H + bn;
        bR0 = *(const float4*)wsrc;
        bR1 = *(const float4*)(wsrc + 4);
    }

    for (int it = 0; it < NKT; it++) {
        // split + store to smem
        {
            float h0 = tf32_rna(aR.x), h1 = tf32_rna(aR.y),
                  h2 = tf32_rna(aR.z), h3 = tf32_rna(aR.w);
            Ah[am][akq+0] = h0; Ah[am][akq+1] = h1; Ah[am][akq+2] = h2; Ah[am][akq+3] = h3;
            Al[am][akq+0] = tf32_rna(aR.x - h0); Al[am][akq+1] = tf32_rna(aR.y - h1);
            Al[am][akq+2] = tf32_rna(aR.z - h2); Al[am][akq+3] = tf32_rna(aR.w - h3);

            float p0 = tf32_rna(bR0.x), p1 = tf32_rna(bR0.y),
                  p2 = tf32_rna(bR0.z), p3 = tf32_rna(bR0.w);
            float p4 = tf32_rna(bR1.x), p5 = tf32_rna(bR1.y),
                  p6 = tf32_rna(bR1.z), p7 = tf32_rna(bR1.w);
            Bh[bk][bn+0] = p0; Bh[bk][bn+1] = p1; Bh[bk][bn+2] = p2; Bh[bk][bn+3] = p3;
            Bh[bk][bn+4] = p4; Bh[bk][bn+5] = p5; Bh[bk][bn+6] = p6; Bh[bk][bn+7] = p7;
            Bl[bk][bn+0] = tf32_rna(bR0.x - p0); Bl[bk][bn+1] = tf32_rna(bR0.y - p1);
            Bl[bk][bn+2] = tf32_rna(bR0.z - p2); Bl[bk][bn+3] = tf32_rna(bR0.w - p3);
            Bl[bk][bn+4] = tf32_rna(bR1.x - p4); Bl[bk][bn+5] = tf32_rna(bR1.y - p5);
            Bl[bk][bn+6] = tf32_rna(bR1.z - p6); Bl[bk][bn+7] = tf32_rna(bR1.w - p7);
        }
        __syncthreads();

        // prefetch next tile
        if (it + 1 < NKT) {
            int k0n = (it + 1) * 16;
            int k = k0n + akq;
            aR = *(const float4*)((k < H ? rowx : rowF) + k);
            const float* wsrc = Wall + (size_t)(k0n + bk) * H + bn;
            bR0 = *(const float4*)wsrc;
            bR1 = *(const float4*)(wsrc + 4);
        }

        // compute: 2 k8 sub-steps
#pragma unroll
        for (int ks = 0; ks < 16; ks += 8) {
            uint32_t ah[2][4], al[2][4], bhf[4][2], blf[4][2];
#pragma unroll
            for (int mt = 0; mt < 2; mt++) {
                int r0 = mb + mt * 16 + g, r1 = r0 + 8;
                ah[mt][0] = __float_as_uint(Ah[r0][ks + c]);
                ah[mt][1] = __float_as_uint(Ah[r1][ks + c]);
                ah[mt][2] = __float_as_uint(Ah[r0][ks + c + 4]);
                ah[mt][3] = __float_as_uint(Ah[r1][ks + c + 4]);
                al[mt][0] = __float_as_uint(Al[r0][ks + c]);
                al[mt][1] = __float_as_uint(Al[r1][ks + c]);
                al[mt][2] = __float_as_uint(Al[r0][ks + c + 4]);
                al[mt][3] = __float_as_uint(Al[r1][ks + c + 4]);
            }
#pragma unroll
            for (int nt = 0; nt < 4; nt++) {
                int nc = nb + nt * 8 + g;
                bhf[nt][0] = __float_as_uint(Bh[ks + c][nc]);
                bhf[nt][1] = __float_as_uint(Bh[ks + c + 4][nc]);
                blf[nt][0] = __float_as_uint(Bl[ks + c][nc]);
                blf[nt][1] = __float_as_uint(Bl[ks + c + 4][nc]);
            }
#pragma unroll
            for (int mt = 0; mt < 2; mt++)
#pragma unroll
                for (int nt = 0; nt < 4; nt++) {
                    mma8(acc[mt][nt], al[mt], bhf[nt]);   // lo*hi
                    mma8(acc[mt][nt], ah[mt], blf[nt]);   // hi*lo
                    mma8(acc[mt][nt], ah[mt], bhf[nt]);   // hi*hi
                }
        }
        __syncthreads();
    }

    // epilogue
#pragma unroll
    for (int mt = 0; mt < 2; mt++) {
        int r0 = m0 + mb + mt * 16 + g;
        int r1 = r0 + 8;
        float cf0 = (r0 < NN) ? cntf[r0] : 0.f;
        float cf1 = (r1 < NN) ? cntf[r1] : 0.f;
#pragma unroll
        for (int nt = 0; nt < 4; nt++) {
            int col = nb + nt * 8 + 2 * c;
            float bx0 = bx[col], bx1 = bx[col + 1];
            float bm0 = bmx[col], bm1 = bmx[col + 1];
            if (r0 < NN) {
                float v0 = leaky(acc[mt][nt][0] + bx0 + cf0 * bm0);
                float v1 = leaky(acc[mt][nt][1] + bx1 + cf0 * bm1);
                if (resid) {
                    v0 = leaky(resid[(size_t)r0 * H + col] + v0);
                    v1 = leaky(resid[(size_t)r0 * H + col + 1] + v1);
                }
                *(float2*)&xout[(size_t)r0 * H + col] = make_float2(v0, v1);
            }
            if (r1 < NN) {
                float v2 = leaky(acc[mt][nt][2] + bx0 + cf1 * bm0);
                float v3 = leaky(acc[mt][nt][3] + bx1 + cf1 * bm1);
                if (resid) {
                    v2 = leaky(resid[(size_t)r1 * H + col] + v2);
                    v3 = leaky(resid[(size_t)r1 * H + col + 1] + v3);
                }
                *(float2*)&xout[(size_t)r1 * H + col] = make_float2(v2, v3);
            }
        }
    }
}

// ---------------- launch ----------------
extern "C" void kernel_launch(void* const* d_in, const int* in_sizes, int n_in,
                              void* d_out, int out_size) {
    const float* x   = (const float*)d_in[0];
    const float* pos = (const float*)d_in[1];
    const int*   ei  = (const int*)d_in[2];
    const float* ea  = (const float*)d_in[3];
    const float* Wm  = (const float*)d_in[4];
    const float* bm  = (const float*)d_in[5];
    // d_in[6] = Wp, d_in[7] = bp : dead code (alpha unused)
    const float* Wx  = (const float*)d_in[8];
    const float* bx  = (const float*)d_in[9];
    float* out = (float*)d_out;

    float *F, *xb, *pb, *cntf, *Wall, *bmx;
    int *cnt, *rowbeg, *cursor, *colj, *total;
    cudaGetSymbolAddress((void**)&F,      g_F);
    cudaGetSymbolAddress((void**)&xb,     g_xbuf);
    cudaGetSymbolAddress((void**)&pb,     g_posbuf);
    cudaGetSymbolAddress((void**)&cnt,    g_cnt);
    cudaGetSymbolAddress((void**)&rowbeg, g_rowbeg);
    cudaGetSymbolAddress((void**)&cursor, g_cursor);
    cudaGetSymbolAddress((void**)&colj,   g_colj);
    cudaGetSymbolAddress((void**)&cntf,   g_cntf);
    cudaGetSymbolAddress((void**)&total,  g_total);
    cudaGetSymbolAddress((void**)&Wall,   g_Wall);
    cudaGetSymbolAddress((void**)&bmx,    g_bmx);

    // preamble: CSR build (order-free segments) + weight folding
    zero_init<<<(NN * 16 + 255) / 256, 256>>>(F, cnt, total);
    edge_pre<<<(NE * 16 + 255) / 256, 256>>>(ei, ea, cnt, F);
    alloc_rows<<<(NN + 255) / 256, 256>>>(cnt, rowbeg, cursor, cntf, total);
    build_csr<<<(NE + 255) / 256, 256>>>(ei, cursor, colj);
    {
        dim3 gp(NLAYER, KA + 1);
        prep_weights<<<gp, 128>>>(Wm, bm, Wx, Wall, bmx);
    }

    const float* curx = x;
    const float* curp = pos;
    for (int l = 0; l < NLAYER; l++) {
        bool last = (l == NLAYER - 1);
        float* nx = last ? out : xb + (size_t)(l & 1) * NN * H;
        float* np = last ? out + (size_t)NN * H : pb + (size_t)(l & 1) * NN * 3;

        csr_layer<<<(NN * 32 + 255) / 256, 256>>>(curx, curp, rowbeg, colj, cntf, F, np);
        fused_layer_gemm<<<(NN + 63) / 64, 256>>>(curx, F, Wall + (size_t)l * KA * H,
                                                  bx + (size_t)l * H, bmx + l * H,
                                                  cntf, last ? x : nullptr, nx);
        curx = nx;
        curp = np;
    }
}